// round 14
// baseline (speedup 1.0000x reference)
#include <cuda_runtime.h>
#include <stdint.h>

#define D_FEAT   256
#define D4       (D_FEAT / 4)     // 64 float4 per x row
#define OUTW     (2 * D_FEAT)     // 512 floats per output row
#define MAX_N    32768
#define MAX_B    8192
#define CAP      128              // slots per destination row (mean deg ~16, max ~45)
#define MAX_SP   65536            // spill capacity (normally 0 used)

// Scratch (no cudaMalloc allowed) — device globals
__device__ int   g_deg[MAX_N];
__device__ int   g_cntrow[MAX_B];
__device__ int   g_spill;
__device__ int   g_slots[MAX_B * CAP];
__device__ int2  g_sp_edge[MAX_SP];

__device__ __forceinline__ int load_idx(const void* ei, long long i, int is64) {
    return is64 ? (int)((const long long*)ei)[i] : ((const int*)ei)[i];
}

__device__ __forceinline__ void fma4(float4& a, float w, const float4& v) {
    a.x += w * v.x; a.y += w * v.y; a.z += w * v.z; a.w += w * v.w;
}

// ---------------------------------------------------------------------------
// 1. build: deg[src]++ over all edges; bucket src into dst slots (dst < batch).
//    Each CTA self-detects the index dtype from the first 256 entries
//    (race-benign shared flag; identical verdict in every CTA).
__global__ void k_build(const void* __restrict__ ei, int E, int n, int batch) {
    __shared__ int s_is64;
    if (threadIdx.x == 0) s_is64 = 1;
    __syncthreads();
    {
        int K = min(E, 256);
        if ((int)threadIdx.x < K) {
            long long v = ((const long long*)ei)[threadIdx.x];
            if (v < 0 || v >= (long long)n) s_is64 = 0;   // benign race: all write 0
        }
    }
    __syncthreads();
    const int is64 = s_is64;

    int i = blockIdx.x * blockDim.x + threadIdx.x;
    if (i >= E) return;
    int src = load_idx(ei, i, is64);
    int dst = load_idx(ei, (long long)E + i, is64);
    atomicAdd(&g_deg[src], 1);
    if (dst < batch) {
        int slot = atomicAdd(&g_cntrow[dst], 1);
        if (slot < CAP) {
            g_slots[dst * CAP + slot] = src;
        } else {
            int p = atomicAdd(&g_spill, 1);
            if (p < MAX_SP) g_sp_edge[p] = make_int2(src, dst);
        }
    }
}

// ---------------------------------------------------------------------------
// 2. gather: one warp per output row (R7 form, verbatim). Writes every output
//    element exactly once (x copy + aggregated half). Rows that overflowed CAP
//    fold their spilled edges in-register (only owning warp -> no race).
__global__ void __launch_bounds__(256) k_gather(const float4* __restrict__ x4,
                                                float4* __restrict__ out4,
                                                int batch) {
    int row  = (blockIdx.x * blockDim.x + threadIdx.x) >> 5;
    int lane = threadIdx.x & 31;
    if (row >= batch) return;

    int mraw = g_cntrow[row];
    int m = (mraw > CAP) ? CAP : mraw;
    int dr = g_deg[row];
    float disr = (dr > 0) ? rsqrtf((float)dr) : 0.0f;

    float4 a0 = make_float4(0.f, 0.f, 0.f, 0.f);
    float4 a1 = make_float4(0.f, 0.f, 0.f, 0.f);

    const int* srow = g_slots + row * CAP;
    for (int base = 0; base < m; base += 32) {
        int e = base + lane;
        int cnt = min(32, m - base);
        int   psrc = 0;
        float pw   = 0.0f;
        if (e < m) {
            psrc = srow[e];
            pw = rsqrtf((float)g_deg[psrc]) * disr;   // deg[src] >= 1 always
        }
        for (int t = 0; t < cnt; t++) {
            int   s  = __shfl_sync(0xffffffff, psrc, t);
            float ww = __shfl_sync(0xffffffff, pw, t);
            const float4* xs = x4 + (size_t)s * D4;
            float4 v0 = __ldg(&xs[lane]);
            float4 v1 = __ldg(&xs[lane + 32]);
            fma4(a0, ww, v0);
            fma4(a1, ww, v1);
        }
    }

    if (mraw > CAP) {
        int sp = g_spill;
        if (sp > MAX_SP) sp = MAX_SP;
        for (int base = 0; base < sp; base += 32) {
            int e = base + lane;
            int cnt = min(32, sp - base);
            int   psrc = 0;
            float pw   = 0.0f;
            if (e < sp) {
                int2 ed = g_sp_edge[e];
                if (ed.y == row) {
                    psrc = ed.x;
                    pw = rsqrtf((float)g_deg[psrc]) * disr;
                }
            }
            for (int t = 0; t < cnt; t++) {
                float ww = __shfl_sync(0xffffffff, pw, t);
                if (ww == 0.0f) continue;
                int s = __shfl_sync(0xffffffff, psrc, t);
                const float4* xs = x4 + (size_t)s * D4;
                float4 v0 = __ldg(&xs[lane]);
                float4 v1 = __ldg(&xs[lane + 32]);
                fma4(a0, ww, v0);
                fma4(a1, ww, v1);
            }
        }
    }

    const float4* xd = x4 + (size_t)row * D4;
    float4* o = out4 + (size_t)row * (OUTW / 4);
    o[lane]      = __ldg(&xd[lane]);
    o[lane + 32] = __ldg(&xd[lane + 32]);
    o[lane + 64] = a0;
    o[lane + 96] = a1;
}

// ---------------------------------------------------------------------------
extern "C" void kernel_launch(void* const* d_in, const int* in_sizes, int n_in,
                              void* d_out, int out_size) {
    // Identify inputs by element count (robust to metadata ordering).
    int ix = 0, ie = -1;
    for (int i = 1; i < n_in; i++)
        if (in_sizes[i] > in_sizes[ix]) ix = i;
    for (int i = 0; i < n_in; i++) {
        if (i == ix || in_sizes[i] <= 1) continue;
        if (ie < 0 || in_sizes[i] > in_sizes[ie]) ie = i;
    }
    if (ie < 0) ie = (ix == 0) ? 1 : 0;

    const float* x  = (const float*)d_in[ix];
    const void*  ei = d_in[ie];

    int n     = in_sizes[ix] / D_FEAT;         // 20000
    int E     = in_sizes[ie] / 2;              // 320000
    int batch = out_size / OUTW;               // 4096

    // Zero counters via graph memset nodes (copy-engine path; no kernel ramp).
    void *p_deg = 0, *p_cnt = 0, *p_spill = 0;
    cudaGetSymbolAddress(&p_deg,   g_deg);
    cudaGetSymbolAddress(&p_cnt,   g_cntrow);
    cudaGetSymbolAddress(&p_spill, g_spill);
    cudaMemsetAsync(p_deg,   0, (size_t)n * sizeof(int));
    cudaMemsetAsync(p_cnt,   0, (size_t)batch * sizeof(int));
    cudaMemsetAsync(p_spill, 0, sizeof(int));

    k_build<<<(E + 255) / 256, 256>>>(ei, E, n, batch);

    long long gthreads = (long long)batch * 32;
    k_gather<<<(int)((gthreads + 255) / 256), 256>>>((const float4*)x,
                                                     (float4*)d_out, batch);
}

// round 15
// speedup vs baseline: 1.1975x; 1.1975x over previous
#include <cuda_runtime.h>
#include <stdint.h>

#define D_FEAT   256
#define D4       (D_FEAT / 4)     // 64 float4 per x row
#define OUTW     (2 * D_FEAT)     // 512 floats per output row
#define MAX_N    32768
#define MAX_B    8192
#define CAP      128              // slots per destination row (mean deg ~16, max ~45)
#define MAX_SP   65536            // spill capacity (normally 0 used)
#define NT       256
#define MAX_CTA_PER_SM 4

// One contiguous counter block -> single memset node zeroes everything.
//   [0, MAX_N)                 : deg
//   [MAX_N, MAX_N+MAX_B)       : cntrow
//   [MAX_N+MAX_B]              : spill count
#define CNT_TOTAL (MAX_N + MAX_B + 1)
__device__ int   g_counters[CNT_TOTAL];
#define g_deg     (g_counters)
#define g_cntrow  (g_counters + MAX_N)
#define g_spillp  (g_counters + MAX_N + MAX_B)

__device__ int   g_slots[MAX_B * CAP];
__device__ int2  g_sp_edge[MAX_SP];

// generation-based grid barrier state (monotonic across graph replays)
__device__ int           g_bar_count;
__device__ volatile int  g_bar_gen;

__device__ __forceinline__ void grid_barrier(int nblocks) {
    __syncthreads();
    if (threadIdx.x == 0) {
        int gen = g_bar_gen;
        __threadfence();                       // make prior writes visible
        if (atomicAdd(&g_bar_count, 1) == nblocks - 1) {
            g_bar_count = 0;
            __threadfence();
            g_bar_gen = gen + 1;               // release
        } else {
            while (g_bar_gen == gen) __nanosleep(32);
            __threadfence();                   // acquire
        }
    }
    __syncthreads();
}

__device__ __forceinline__ int load_idx(const void* ei, long long i, int is64) {
    return is64 ? (int)((const long long*)ei)[i] : ((const int*)ei)[i];
}

__device__ __forceinline__ void fma4(float4& a, float w, const float4& v) {
    a.x += w * v.x; a.y += w * v.y; a.z += w * v.z; a.w += w * v.w;
}

// ---------------------------------------------------------------------------
__global__ void __launch_bounds__(NT, MAX_CTA_PER_SM)
k_fused(const void* __restrict__ ei, const float4* __restrict__ x4,
        float4* __restrict__ out4, int E, int n, int batch, int nblocks) {
    const int tid      = blockIdx.x * NT + threadIdx.x;
    const int nthreads = nblocks * NT;

    // ---- dtype detection (per-CTA, race-benign, L2-hot after first CTA) -----
    __shared__ int s_is64;
    if (threadIdx.x == 0) s_is64 = 1;
    __syncthreads();
    {
        int K = min(E, 256);
        if ((int)threadIdx.x < K) {
            long long v = ((const long long*)ei)[threadIdx.x];
            if (v < 0 || v >= (long long)n) s_is64 = 0;   // all writers write 0
        }
    }
    __syncthreads();
    const int is64 = s_is64;

    // ---- Phase B: build deg + slot buckets (R7 scalar form, verbatim) -------
    for (int i = tid; i < E; i += nthreads) {
        int src = load_idx(ei, i, is64);
        int dst = load_idx(ei, (long long)E + i, is64);
        atomicAdd(&g_deg[src], 1);
        if (dst < batch) {
            int slot = atomicAdd(&g_cntrow[dst], 1);
            if (slot < CAP) {
                g_slots[dst * CAP + slot] = src;
            } else {
                int p = atomicAdd(g_spillp, 1);
                if (p < MAX_SP) g_sp_edge[p] = make_int2(src, dst);
            }
        }
    }

    grid_barrier(nblocks);

    // ---- Phase C: gather, one warp per row (R7 form, verbatim) --------------
    const int lane   = threadIdx.x & 31;
    const int gwarp  = tid >> 5;
    const int nwarps = nthreads >> 5;

    for (int row = gwarp; row < batch; row += nwarps) {
        int mraw = g_cntrow[row];
        int m = (mraw > CAP) ? CAP : mraw;
        int dr = g_deg[row];
        float disr = (dr > 0) ? rsqrtf((float)dr) : 0.0f;

        float4 a0 = make_float4(0.f, 0.f, 0.f, 0.f);
        float4 a1 = make_float4(0.f, 0.f, 0.f, 0.f);

        const int* srow = g_slots + row * CAP;
        for (int base = 0; base < m; base += 32) {
            int e = base + lane;
            int cnt = min(32, m - base);
            int   psrc = 0;
            float pw   = 0.0f;
            if (e < m) {
                psrc = srow[e];
                pw = rsqrtf((float)g_deg[psrc]) * disr;   // deg[src] >= 1 always
            }
            for (int t = 0; t < cnt; t++) {
                int   s  = __shfl_sync(0xffffffff, psrc, t);
                float ww = __shfl_sync(0xffffffff, pw, t);
                const float4* xs = x4 + (size_t)s * D4;
                float4 v0 = __ldg(&xs[lane]);
                float4 v1 = __ldg(&xs[lane + 32]);
                fma4(a0, ww, v0);
                fma4(a1, ww, v1);
            }
        }

        // Overflow fold (only the owning warp touches its spilled edges).
        if (mraw > CAP) {
            int sp = *g_spillp;
            if (sp > MAX_SP) sp = MAX_SP;
            for (int base = 0; base < sp; base += 32) {
                int e = base + lane;
                int cnt = min(32, sp - base);
                int   psrc = 0;
                float pw   = 0.0f;
                if (e < sp) {
                    int2 ed = g_sp_edge[e];
                    if (ed.y == row) {
                        psrc = ed.x;
                        pw = rsqrtf((float)g_deg[psrc]) * disr;
                    }
                }
                for (int t = 0; t < cnt; t++) {
                    float ww = __shfl_sync(0xffffffff, pw, t);
                    if (ww == 0.0f) continue;
                    int s = __shfl_sync(0xffffffff, psrc, t);
                    const float4* xs = x4 + (size_t)s * D4;
                    float4 v0 = __ldg(&xs[lane]);
                    float4 v1 = __ldg(&xs[lane + 32]);
                    fma4(a0, ww, v0);
                    fma4(a1, ww, v1);
                }
            }
        }

        const float4* xd = x4 + (size_t)row * D4;
        float4* o = out4 + (size_t)row * (OUTW / 4);
        o[lane]      = __ldg(&xd[lane]);
        o[lane + 32] = __ldg(&xd[lane + 32]);
        o[lane + 64] = a0;
        o[lane + 96] = a1;
    }
}

// ---------------------------------------------------------------------------
extern "C" void kernel_launch(void* const* d_in, const int* in_sizes, int n_in,
                              void* d_out, int out_size) {
    // Identify inputs by element count (robust to metadata ordering).
    int ix = 0, ie = -1;
    for (int i = 1; i < n_in; i++)
        if (in_sizes[i] > in_sizes[ix]) ix = i;
    for (int i = 0; i < n_in; i++) {
        if (i == ix || in_sizes[i] <= 1) continue;
        if (ie < 0 || in_sizes[i] > in_sizes[ie]) ie = i;
    }
    if (ie < 0) ie = (ix == 0) ? 1 : 0;

    const float* x  = (const float*)d_in[ix];
    const void*  ei = d_in[ie];

    int n     = in_sizes[ix] / D_FEAT;         // 20000
    int E     = in_sizes[ie] / 2;              // 320000
    int batch = out_size / OUTW;               // 4096

    // ONE memset node zeroes deg + cntrow + spill (contiguous block).
    void* p_cnt = 0;
    cudaGetSymbolAddress(&p_cnt, g_counters);
    cudaMemsetAsync(p_cnt, 0, (size_t)CNT_TOTAL * sizeof(int));

    // Co-resident grid: query achievable occupancy so the spin barrier is safe.
    static int nblocks = 0;
    if (nblocks == 0) {
        int smCount = 0;
        if (cudaDeviceGetAttribute(&smCount, cudaDevAttrMultiProcessorCount, 0)
            != cudaSuccess || smCount <= 0)
            smCount = 148;
        int perSM = 0;
        if (cudaOccupancyMaxActiveBlocksPerMultiprocessor(&perSM, k_fused, NT, 0)
            != cudaSuccess || perSM <= 0)
            perSM = 1;
        if (perSM > MAX_CTA_PER_SM) perSM = MAX_CTA_PER_SM;
        nblocks = smCount * perSM;
    }

    k_fused<<<nblocks, NT>>>(ei, (const float4*)x, (float4*)d_out,
                             E, n, batch, nblocks);
}